// round 3
// baseline (speedup 1.0000x reference)
#include <cuda_runtime.h>
#include <cstdint>

#define BATCH  64
#define MROWS  2048
#define DIM    512
#define CHUNKS 64            // MROWS / 32 rows-per-block

// Per-(batch,chunk) packed partial: (dist2_bits << 32) | (0xFFFFFFFF - m).
// Every slot is written every launch -> no init kernel needed.
__device__ unsigned long long g_part[BATCH * CHUNKS];
// Per-batch completion counter. Zero at module load; the last block for a
// batch resets it to 0 after use, so the invariant holds across graph replays.
__device__ unsigned int g_count[BATCH];

static __device__ __forceinline__ unsigned long long umax64(
    unsigned long long a, unsigned long long b) { return a > b ? a : b; }

// Grid: (CHUNKS, BATCH). Block: 256 threads = 8 warps; each warp handles 4 rows.
__global__ __launch_bounds__(256, 2) void knn_fused_kernel(
    const float* __restrict__ inputs,
    const float* __restrict__ buffer,
    float* __restrict__ out)
{
    __shared__ float4 q4s[DIM / 4];              // 2 KB query
    __shared__ unsigned long long wbest[8];
    __shared__ unsigned int s_is_last;
    __shared__ unsigned int s_m;

    const int b     = blockIdx.y;
    const int chunk = blockIdx.x;
    const int tid   = threadIdx.x;
    const int warp  = tid >> 5;
    const int lane  = tid & 31;

    // Stage query into smem, then into registers (one-time cost).
    const float4* qin = reinterpret_cast<const float4*>(inputs + (size_t)b * DIM);
    for (int i = tid; i < DIM / 4; i += blockDim.x) q4s[i] = qin[i];
    __syncthreads();

    float4 q[4];
    #pragma unroll
    for (int j = 0; j < 4; j++) q[j] = q4s[lane + 32 * j];

    // ---- Distance: hoist ALL 16 LDG.128 per lane (MLP=16), then compute ----
    const int m0 = chunk * 32 + warp * 4;
    const float* base = buffer + ((size_t)b * MROWS + m0) * DIM;

    float4 v[4][4];
    #pragma unroll
    for (int k = 0; k < 4; k++) {
        const float4* row = reinterpret_cast<const float4*>(base + (size_t)k * DIM);
        #pragma unroll
        for (int j = 0; j < 4; j++)
            v[k][j] = row[lane + 32 * j];        // coalesced 128B/warp per load
    }

    unsigned long long local = 0ULL;
    #pragma unroll
    for (int k = 0; k < 4; k++) {
        float acc = 0.0f;
        #pragma unroll
        for (int j = 0; j < 4; j++) {
            float d0 = v[k][j].x - q[j].x;
            float d1 = v[k][j].y - q[j].y;
            float d2 = v[k][j].z - q[j].z;
            float d3 = v[k][j].w - q[j].w;
            acc = fmaf(d0, d0, acc);
            acc = fmaf(d1, d1, acc);
            acc = fmaf(d2, d2, acc);
            acc = fmaf(d3, d3, acc);
        }
        #pragma unroll
        for (int off = 16; off > 0; off >>= 1)
            acc += __shfl_xor_sync(0xFFFFFFFFu, acc, off);

        // dist2 >= 0 -> float bits order-preserving; ~m tie-breaks to smallest m.
        unsigned long long pack =
            ((unsigned long long)__float_as_uint(acc) << 32) |
            (unsigned long long)(0xFFFFFFFFu - (unsigned)(m0 + k));
        local = umax64(local, pack);
    }

    if (lane == 0) wbest[warp] = local;
    __syncthreads();

    // ---- Block reduce + completion protocol ----
    if (tid == 0) {
        unsigned long long blk = wbest[0];
        #pragma unroll
        for (int w = 1; w < 8; w++) blk = umax64(blk, wbest[w]);
        g_part[b * CHUNKS + chunk] = blk;
        __threadfence();                          // publish partial before count
        unsigned int old = atomicAdd(&g_count[b], 1u);
        s_is_last = (old == CHUNKS - 1) ? 1u : 0u;
    }
    __syncthreads();

    // ---- Last block for this batch: reduce partials + gather winning row ----
    if (s_is_last) {
        if (warp == 0) {
            __threadfence();                      // acquire partials
            unsigned long long a = g_part[b * CHUNKS + lane];
            unsigned long long c = g_part[b * CHUNKS + 32 + lane];
            unsigned long long mx = umax64(a, c);
            #pragma unroll
            for (int off = 16; off > 0; off >>= 1) {
                unsigned long long o = __shfl_xor_sync(0xFFFFFFFFu, mx, off);
                mx = umax64(mx, o);
            }
            if (lane == 0) {
                s_m = 0xFFFFFFFFu - (unsigned)(mx & 0xFFFFFFFFu);
                g_count[b] = 0;                   // restore invariant for next replay
            }
        }
        __syncthreads();
        const unsigned m = s_m;
        const float4* src = reinterpret_cast<const float4*>(
            buffer + ((size_t)b * MROWS + m) * DIM);
        float4* dst = reinterpret_cast<float4*>(out + (size_t)b * DIM);
        if (tid < DIM / 4) dst[tid] = src[tid];
    }
}

extern "C" void kernel_launch(void* const* d_in, const int* in_sizes, int n_in,
                              void* d_out, int out_size)
{
    const float* inputs = (const float*)d_in[0];   // [B, D]
    const float* buffer = (const float*)d_in[1];   // [B, M, D]
    float* out = (float*)d_out;                    // [B, D]

    dim3 grid(CHUNKS, BATCH);                      // 64 x 64 = 4096 blocks
    knn_fused_kernel<<<grid, 256>>>(inputs, buffer, out);
}

// round 6
// speedup vs baseline: 1.0907x; 1.0907x over previous
#include <cuda_runtime.h>
#include <cstdint>

#define BATCH  64
#define MROWS  2048
#define DIM    512
#define CHUNKS 64            // MROWS / 32 rows-per-block

// Per-(batch,chunk) packed partial: (dist2_bits << 32) | (0xFFFFFFFF - m).
// Every slot is written every launch -> no init kernel needed.
__device__ unsigned long long g_part[BATCH * CHUNKS];
// Per-batch completion counter. Zero at module load; the last block for a
// batch resets it to 0 after use, preserving the invariant across graph replays.
__device__ unsigned int g_count[BATCH];

static __device__ __forceinline__ unsigned long long umax64(
    unsigned long long a, unsigned long long b) { return a > b ? a : b; }

// Grid: (CHUNKS, BATCH). Block: 256 threads = 8 warps; each warp handles 4 rows.
// Low-register inner loop (MLP=4/warp) + 4 CTAs/SM for outstanding-load volume.
__global__ __launch_bounds__(256, 4) void knn_fused_kernel(
    const float* __restrict__ inputs,
    const float* __restrict__ buffer,
    float* __restrict__ out)
{
    __shared__ float4 q4s[DIM / 4];              // 2 KB query
    __shared__ unsigned long long wbest[8];
    __shared__ unsigned int s_is_last;
    __shared__ unsigned int s_m;

    const int b     = blockIdx.y;
    const int chunk = blockIdx.x;
    const int tid   = threadIdx.x;
    const int warp  = tid >> 5;
    const int lane  = tid & 31;

    // Stage query into smem (coalesced float4).
    const float4* qin = reinterpret_cast<const float4*>(inputs + (size_t)b * DIM);
    for (int i = tid; i < DIM / 4; i += blockDim.x) q4s[i] = qin[i];
    __syncthreads();

    const int m0 = chunk * 32 + warp * 4;
    const float* base = buffer + ((size_t)b * MROWS + m0) * DIM;

    unsigned long long local = 0ULL;
    #pragma unroll
    for (int k = 0; k < 4; k++) {
        const float4* row = reinterpret_cast<const float4*>(base + (size_t)k * DIM);
        // 4 independent LDG.128 per lane, coalesced 512B/warp per load.
        float4 v0 = row[lane];
        float4 v1 = row[lane + 32];
        float4 v2 = row[lane + 64];
        float4 v3 = row[lane + 96];
        float4 q0 = q4s[lane];
        float4 q1 = q4s[lane + 32];
        float4 q2 = q4s[lane + 64];
        float4 q3 = q4s[lane + 96];

        float acc = 0.0f;
        float d;
        d = v0.x - q0.x; acc = fmaf(d, d, acc);
        d = v0.y - q0.y; acc = fmaf(d, d, acc);
        d = v0.z - q0.z; acc = fmaf(d, d, acc);
        d = v0.w - q0.w; acc = fmaf(d, d, acc);
        d = v1.x - q1.x; acc = fmaf(d, d, acc);
        d = v1.y - q1.y; acc = fmaf(d, d, acc);
        d = v1.z - q1.z; acc = fmaf(d, d, acc);
        d = v1.w - q1.w; acc = fmaf(d, d, acc);
        d = v2.x - q2.x; acc = fmaf(d, d, acc);
        d = v2.y - q2.y; acc = fmaf(d, d, acc);
        d = v2.z - q2.z; acc = fmaf(d, d, acc);
        d = v2.w - q2.w; acc = fmaf(d, d, acc);
        d = v3.x - q3.x; acc = fmaf(d, d, acc);
        d = v3.y - q3.y; acc = fmaf(d, d, acc);
        d = v3.z - q3.z; acc = fmaf(d, d, acc);
        d = v3.w - q3.w; acc = fmaf(d, d, acc);

        #pragma unroll
        for (int off = 16; off > 0; off >>= 1)
            acc += __shfl_xor_sync(0xFFFFFFFFu, acc, off);

        // dist2 >= 0 -> float bits order-preserving; ~m tie-breaks to smallest m.
        unsigned long long pack =
            ((unsigned long long)__float_as_uint(acc) << 32) |
            (unsigned long long)(0xFFFFFFFFu - (unsigned)(m0 + k));
        local = umax64(local, pack);
    }

    if (lane == 0) wbest[warp] = local;
    __syncthreads();

    // ---- Block reduce + completion protocol ----
    if (tid == 0) {
        unsigned long long blk = wbest[0];
        #pragma unroll
        for (int w = 1; w < 8; w++) blk = umax64(blk, wbest[w]);
        g_part[b * CHUNKS + chunk] = blk;
        __threadfence();                          // publish partial before count
        unsigned int old = atomicAdd(&g_count[b], 1u);
        s_is_last = (old == CHUNKS - 1) ? 1u : 0u;
    }
    __syncthreads();

    // ---- Last block for this batch: reduce partials + gather winning row ----
    if (s_is_last) {
        if (warp == 0) {
            __threadfence();                      // acquire partials
            unsigned long long a = g_part[b * CHUNKS + lane];
            unsigned long long c = g_part[b * CHUNKS + 32 + lane];
            unsigned long long mx = umax64(a, c);
            #pragma unroll
            for (int off = 16; off > 0; off >>= 1) {
                unsigned long long o = __shfl_xor_sync(0xFFFFFFFFu, mx, off);
                mx = umax64(mx, o);
            }
            if (lane == 0) {
                s_m = 0xFFFFFFFFu - (unsigned)(mx & 0xFFFFFFFFu);
                g_count[b] = 0;                   // restore invariant for next replay
            }
        }
        __syncthreads();
        const unsigned m = s_m;
        const float4* src = reinterpret_cast<const float4*>(
            buffer + ((size_t)b * MROWS + m) * DIM);
        float4* dst = reinterpret_cast<float4*>(out + (size_t)b * DIM);
        if (tid < DIM / 4) dst[tid] = src[tid];
    }
}

extern "C" void kernel_launch(void* const* d_in, const int* in_sizes, int n_in,
                              void* d_out, int out_size)
{
    const float* inputs = (const float*)d_in[0];   // [B, D]
    const float* buffer = (const float*)d_in[1];   // [B, M, D]
    float* out = (float*)d_out;                    // [B, D]

    dim3 grid(CHUNKS, BATCH);                      // 64 x 64 = 4096 blocks
    knn_fused_kernel<<<grid, 256>>>(inputs, buffer, out);
}